// round 16
// baseline (speedup 1.0000x reference)
#include <cuda_runtime.h>
#include <cuda_fp16.h>
#include <math.h>
#include <cstdint>

#define B_ 8
#define N_ 8192
#define D_ 256

// ---------------- device scratch ----------------
__device__ float g_WvT[D_ * D_];
__device__ float g_G[B_ * D_ * D_];
__device__ float g_T[B_ * D_ * D_];
__device__ float g_S[B_ * D_ * D_];
__device__ float g_C[B_ * D_ * D_];          // C[d][e]
__device__ float g_sk[B_ * D_];
__device__ float g_sv[B_ * D_];
__device__ float g_u[B_ * D_];
__device__ float g_w[B_ * D_];
__device__ float g_r[B_ * D_];
__device__ float g_cnt[B_];
__device__ float g_biasflag;                 // |bk|+|bv|
__device__ float g_biasflagq;                // |bq|
__device__ unsigned char g_mask8[B_ * N_];
__device__ int g_notint, g_notfloat;
__device__ __align__(16) __half g_CTh[B_ * D_ * D_];
__device__ __align__(16) __half g_CTl[B_ * D_ * D_];

// ---------------- f32x2 (small SIMT GEMMs) ----------------
__device__ __forceinline__ unsigned long long pack2(float x, float y) {
    unsigned long long r;
    asm("mov.b64 %0, {%1, %2};" : "=l"(r) : "f"(x), "f"(y));
    return r;
}
__device__ __forceinline__ void unpack2(unsigned long long v, float &x, float &y) {
    asm("mov.b64 {%0, %1}, %2;" : "=f"(x), "=f"(y) : "l"(v));
}
__device__ __forceinline__ void ffma2(unsigned long long &d, unsigned long long a,
                                      unsigned long long b) {
    asm("fma.rn.f32x2 %0, %1, %2, %0;" : "+l"(d) : "l"(a), "l"(b));
}

// ---------------- cp.async ----------------
__device__ __forceinline__ void cp16(uint32_t s, const void* g) {
    asm volatile("cp.async.ca.shared.global [%0], [%1], 16;\n" :: "r"(s), "l"(g));
}
__device__ __forceinline__ void cp_commit() { asm volatile("cp.async.commit_group;\n"); }
template <int NW>
__device__ __forceinline__ void cp_wait() {
    asm volatile("cp.async.wait_group %0;\n" :: "n"(NW));
}

// ---------------- mma.sync helpers ----------------
__device__ __forceinline__ void ldsm4t(uint32_t addr, uint32_t &r0, uint32_t &r1,
                                       uint32_t &r2, uint32_t &r3) {
    asm volatile("ldmatrix.sync.aligned.m8n8.x4.trans.shared.b16 {%0,%1,%2,%3}, [%4];"
                 : "=r"(r0), "=r"(r1), "=r"(r2), "=r"(r3) : "r"(addr));
}
__device__ __forceinline__ void mma16816(float* c, uint32_t a0, uint32_t a1,
                                         uint32_t a2, uint32_t a3,
                                         uint32_t b0, uint32_t b1) {
    asm volatile(
        "mma.sync.aligned.m16n8k16.row.col.f32.f16.f16.f32 "
        "{%0,%1,%2,%3}, {%4,%5,%6,%7}, {%8,%9}, {%0,%1,%2,%3};"
        : "+f"(c[0]), "+f"(c[1]), "+f"(c[2]), "+f"(c[3])
        : "r"(a0), "r"(a1), "r"(a2), "r"(a3), "r"(b0), "r"(b1));
}

// unified .trans fragment address: tile stored [k][136] halfs, k-major
__device__ __forceinline__ uint32_t frag_addr(uint32_t tile_base, int lane, int coff) {
    int lrow = (lane & 7) + ((lane & 16) >> 1);
    int lcol = coff + (lane & 8);
    return tile_base + (uint32_t)(lrow * 136 + lcol) * 2;
}

// ---------------- mask dtype detection ----------------
__global__ void k_maskdetect(const void* mp) {
    int i = blockIdx.x * blockDim.x + threadIdx.x;   // [0, 16384)
    int v = ((const int*)mp)[i];
    if (v != 0 && v != 1) atomicOr(&g_notint, 1);
    float f = ((const float*)mp)[i];
    if (!(f == 0.0f || f == 1.0f)) atomicOr(&g_notfloat, 1);
}
__global__ void k_maskconv(const void* mp) {
    int i = blockIdx.x * blockDim.x + threadIdx.x;   // [0, B*N)
    unsigned char m;
    if (!g_notint)        m = (((const int*)mp)[i] != 0);
    else if (!g_notfloat) m = (((const float*)mp)[i] != 0.0f);
    else                  m = (((const unsigned char*)mp)[i] != 0);
    g_mask8[i] = m;
}

// ================= G = K^T V via HMMA, fused fp32->fp16 split =================
// CTA: 128(j) x 128(l), 8 warps (warp 64x32), KS=32, 2-stage fp32 staging,
// single-buffered fp16 tiles. Mask folded in at conversion.
#define GCH 8
#define G_SA  0                        // fp32 staging K: 2 x 16384
#define G_SB  32768                    // fp32 staging V: 2 x 16384
#define G_FAH 65536                    // fp16 tiles (32x136 halfs = 8704 B each)
#define G_FAL (G_FAH + 8704)
#define G_FBH (G_FAH + 2 * 8704)
#define G_FBL (G_FAH + 3 * 8704)
#define G_SMEM (G_FAH + 4 * 8704)      // 100352

__global__ void __launch_bounds__(256) gemm_gram_mma(
    const float* __restrict__ key, const float* __restrict__ val)
{
    extern __shared__ __align__(16) char sm[];
    const uint32_t sb = (uint32_t)__cvta_generic_to_shared(sm);
    const int t = threadIdx.x, lane = t & 31, w = t >> 5;
    const int wj = w & 1, wl = w >> 1;
    const int n0 = blockIdx.x * 128, m0 = blockIdx.y * 128;
    const int b = blockIdx.z >> 3, ch = blockIdx.z & 7;
    const int kbeg = ch * (N_ / GCH);
    const int NIT = (N_ / GCH) / 32;     // 32

    const float* Ak = key + (long)b * N_ * D_;
    const float* Bv = val + (long)b * N_ * D_;
    const unsigned char* mrow = g_mask8 + (long)b * N_ + kbeg;

    // conversion/staging mapping: row k = t>>3 (0..31), col-octet c = t&7
    const int kr = t >> 3, c = t & 7;

    float acc[4][4][4];
#pragma unroll
    for (int i = 0; i < 4; i++)
#pragma unroll
        for (int j = 0; j < 4; j++)
#pragma unroll
            for (int q = 0; q < 4; q++) acc[i][j][q] = 0.0f;

    // prologue: stage 0
    {
        long g0 = (long)(kbeg + kr) * D_;
#pragma unroll
        for (int q = 0; q < 4; q++) {
            uint32_t so = (uint32_t)(kr * 512 + (c + 8 * q) * 16);
            cp16(sb + G_SA + so, Ak + g0 + m0 + (c + 8 * q) * 4);
            cp16(sb + G_SB + so, Bv + g0 + n0 + (c + 8 * q) * 4);
        }
        cp_commit();
    }

    for (int it = 0; it < NIT; it++) {
        const int s = it & 1;
        // mask byte for my conversion row (prefetch before waits)
        const float msc = mrow[it * 32 + kr] ? 0.0f : 1.0f;

        if (it + 1 < NIT) {
            long g1 = (long)(kbeg + (it + 1) * 32 + kr) * D_;
            uint32_t st = (uint32_t)((s ^ 1) * 16384);
#pragma unroll
            for (int q = 0; q < 4; q++) {
                uint32_t so = st + (uint32_t)(kr * 512 + (c + 8 * q) * 16);
                cp16(sb + G_SA + so, Ak + g1 + m0 + (c + 8 * q) * 4);
                cp16(sb + G_SB + so, Bv + g1 + n0 + (c + 8 * q) * 4);
            }
            cp_commit();
            cp_wait<1>();
        } else {
            cp_wait<0>();
        }
        __syncthreads();   // staging s ready; prev iter's ldsm done (tiles free)

        // convert staging s -> fp16 hi/lo tiles [k][136]
#pragma unroll
        for (int q = 0; q < 4; q++) {
            uint32_t so = (uint32_t)(s * 16384 + kr * 512 + (c + 8 * q) * 16);
            uint32_t fo = (uint32_t)(kr * 272 + (c + 8 * q) * 8);
            // A (key) with mask
            float4 v = *(const float4*)(sm + G_SA + so);
            v.x *= msc; v.y *= msc; v.z *= msc; v.w *= msc;
            __half2 h0 = __floats2half2_rn(v.x, v.y);
            __half2 h1 = __floats2half2_rn(v.z, v.w);
            float2 f0 = __half22float2(h0), f1 = __half22float2(h1);
            __half2 l0 = __floats2half2_rn(v.x - f0.x, v.y - f0.y);
            __half2 l1 = __floats2half2_rn(v.z - f1.x, v.w - f1.y);
            uint2 ph; ph.x = *(uint32_t*)&h0; ph.y = *(uint32_t*)&h1;
            uint2 pl; pl.x = *(uint32_t*)&l0; pl.y = *(uint32_t*)&l1;
            *(uint2*)(sm + G_FAH + fo) = ph;
            *(uint2*)(sm + G_FAL + fo) = pl;
            // B (value)
            float4 u = *(const float4*)(sm + G_SB + so);
            __half2 H0 = __floats2half2_rn(u.x, u.y);
            __half2 H1 = __floats2half2_rn(u.z, u.w);
            float2 F0 = __half22float2(H0), F1 = __half22float2(H1);
            __half2 L0 = __floats2half2_rn(u.x - F0.x, u.y - F0.y);
            __half2 L1 = __floats2half2_rn(u.z - F1.x, u.w - F1.y);
            uint2 pH; pH.x = *(uint32_t*)&H0; pH.y = *(uint32_t*)&H1;
            uint2 pL; pL.x = *(uint32_t*)&L0; pL.y = *(uint32_t*)&L1;
            *(uint2*)(sm + G_FBH + fo) = pH;
            *(uint2*)(sm + G_FBL + fo) = pL;
        }
        __syncthreads();   // fp16 tiles ready

#pragma unroll
        for (int h = 0; h < 2; h++) {
            const uint32_t hb = (uint32_t)(h * 4352);
            uint32_t aH[4][4], aL[4][4], bH[4][2], bL[4][2];
#pragma unroll
            for (int mt = 0; mt < 4; mt++) {
                int coff = wj * 64 + mt * 16;
                ldsm4t(frag_addr(sb + G_FAH + hb, lane, coff),
                       aH[mt][0], aH[mt][1], aH[mt][2], aH[mt][3]);
                ldsm4t(frag_addr(sb + G_FAL + hb, lane, coff),
                       aL[mt][0], aL[mt][1], aL[mt][2], aL[mt][3]);
            }
#pragma unroll
            for (int p = 0; p < 2; p++) {
                int coff = wl * 32 + p * 16;
                uint32_t r0, r1, r2, r3;
                ldsm4t(frag_addr(sb + G_FBH + hb, lane, coff), r0, r1, r2, r3);
                bH[2 * p][0] = r0; bH[2 * p][1] = r2;
                bH[2 * p + 1][0] = r1; bH[2 * p + 1][1] = r3;
                ldsm4t(frag_addr(sb + G_FBL + hb, lane, coff), r0, r1, r2, r3);
                bL[2 * p][0] = r0; bL[2 * p][1] = r2;
                bL[2 * p + 1][0] = r1; bL[2 * p + 1][1] = r3;
            }
#pragma unroll
            for (int mt = 0; mt < 4; mt++)
#pragma unroll
                for (int nt = 0; nt < 4; nt++) {
                    mma16816(acc[mt][nt], aH[mt][0], aH[mt][1], aH[mt][2], aH[mt][3],
                             bH[nt][0], bH[nt][1]);
                    mma16816(acc[mt][nt], aH[mt][0], aH[mt][1], aH[mt][2], aH[mt][3],
                             bL[nt][0], bL[nt][1]);
                    mma16816(acc[mt][nt], aL[mt][0], aL[mt][1], aL[mt][2], aL[mt][3],
                             bH[nt][0], bH[nt][1]);
                }
        }
    }

    // epilogue: atomic accumulate into g_G
    const int g = lane >> 2, tig = lane & 3;
    float* Cb = g_G + (long)b * D_ * D_;
#pragma unroll
    for (int mt = 0; mt < 4; mt++)
#pragma unroll
        for (int nt = 0; nt < 4; nt++) {
            int row = m0 + wj * 64 + mt * 16 + g;
            int col = n0 + wl * 32 + nt * 8 + 2 * tig;
            float* cr = Cb + (long)row * D_ + col;
            atomicAdd(cr,              acc[mt][nt][0]);
            atomicAdd(cr + 1,          acc[mt][nt][1]);
            atomicAdd(cr + 8 * D_,     acc[mt][nt][2]);
            atomicAdd(cr + 8 * D_ + 1, acc[mt][nt][3]);
        }
}

// ================= out = query @ C + r via HMMA, fp16 split =================
#define O_STA 0                      // fp32 staging A: 3 x 8192
#define O_FAH 24576                  // fp16 A hi: 2 x 4352
#define O_FAL 33280
#define O_FBH 41984                  // fp16 B hi: 4 x 4352
#define O_FBL 59392
#define O_SMEM 76800

__global__ void __launch_bounds__(256) gemm_out_mma(
    const float* __restrict__ query, float* __restrict__ outp)
{
    extern __shared__ __align__(16) char sm[];
    const uint32_t sb = (uint32_t)__cvta_generic_to_shared(sm);
    const int t = threadIdx.x, lane = t & 31, w = t >> 5;
    const int wj = w & 1, wl = w >> 1;
    const int n0 = blockIdx.x * 128, m0 = blockIdx.y * 128;
    const int b = blockIdx.z;
    const int NIT = D_ / 16;   // 16

    const float* Aq = query + ((long)b * N_ + m0) * D_;
    const __half* Bh = g_CTh + (long)b * D_ * D_;
    const __half* Bl = g_CTl + (long)b * D_ * D_;

    float acc[4][4][4];
#pragma unroll
    for (int i = 0; i < 4; i++)
#pragma unroll
        for (int j = 0; j < 4; j++)
#pragma unroll
            for (int q = 0; q < 4; q++) acc[i][j][q] = 0.0f;

#pragma unroll
    for (int j = 0; j < 3; j++) {
        int k0 = j * 16, as = j % 3, bs = j % 4;
#pragma unroll
        for (int r = 0; r < 2; r++) {
            int idx = t + r * 256, m = idx >> 2, c = idx & 3;
            cp16(sb + O_STA + as * 8192 + (m * 16 + c * 4) * 4,
                 Aq + (long)m * D_ + k0 + c * 4);
        }
        { int kr = t >> 4, c = t & 15;
          cp16(sb + O_FBH + bs * 4352 + (kr * 136 + c * 8) * 2,
               Bh + (long)(k0 + kr) * D_ + n0 + c * 8);
          cp16(sb + O_FBL + bs * 4352 + (kr * 136 + c * 8) * 2,
               Bl + (long)(k0 + kr) * D_ + n0 + c * 8); }
        cp_commit();
    }

    for (int it = 0; it < NIT; it++) {
        const int as = it % 3, bs = it % 4, fs = it & 1;
        cp_wait<2>();
        __syncthreads();
#pragma unroll
        for (int p = 0; p < 4; p++) {
            int idx = t + p * 256;
            int m = idx & 127, kp = idx >> 7;     // kp 0..7
            float2 v = *(const float2*)(sm + O_STA + as * 8192 + (m * 16 + 2 * kp) * 4);
            __half hx = __float2half(v.x);
            __half lx = __float2half(v.x - __half2float(hx));
            __half hy = __float2half(v.y);
            __half ly = __float2half(v.y - __half2float(hy));
            __half* pH = (__half*)(sm + O_FAH + fs * 4352);
            __half* pL = (__half*)(sm + O_FAL + fs * 4352);
            pH[(2 * kp) * 136 + m] = hx;  pH[(2 * kp + 1) * 136 + m] = hy;
            pL[(2 * kp) * 136 + m] = lx;  pL[(2 * kp + 1) * 136 + m] = ly;
        }
        __syncthreads();
        if (it + 3 < NIT) {
            int k0 = (it + 3) * 16, as2 = (it + 3) % 3, bs2 = (it + 3) % 4;
#pragma unroll
            for (int r = 0; r < 2; r++) {
                int idx = t + r * 256, m = idx >> 2, c = idx & 3;
                cp16(sb + O_STA + as2 * 8192 + (m * 16 + c * 4) * 4,
                     Aq + (long)m * D_ + k0 + c * 4);
            }
            { int kr = t >> 4, c = t & 15;
              cp16(sb + O_FBH + bs2 * 4352 + (kr * 136 + c * 8) * 2,
                   Bh + (long)(k0 + kr) * D_ + n0 + c * 8);
              cp16(sb + O_FBL + bs2 * 4352 + (kr * 136 + c * 8) * 2,
                   Bl + (long)(k0 + kr) * D_ + n0 + c * 8); }
        }
        cp_commit();

        uint32_t aH[4][4], aL[4][4], bH[4][2], bL[4][2];
#pragma unroll
        for (int mt = 0; mt < 4; mt++) {
            int coff = wj * 64 + mt * 16;
            ldsm4t(frag_addr(sb + O_FAH + fs * 4352, lane, coff),
                   aH[mt][0], aH[mt][1], aH[mt][2], aH[mt][3]);
            ldsm4t(frag_addr(sb + O_FAL + fs * 4352, lane, coff),
                   aL[mt][0], aL[mt][1], aL[mt][2], aL[mt][3]);
        }
#pragma unroll
        for (int p = 0; p < 2; p++) {
            int coff = wl * 32 + p * 16;
            uint32_t r0, r1, r2, r3;
            ldsm4t(frag_addr(sb + O_FBH + bs * 4352, lane, coff), r0, r1, r2, r3);
            bH[2 * p][0] = r0; bH[2 * p][1] = r2;
            bH[2 * p + 1][0] = r1; bH[2 * p + 1][1] = r3;
            ldsm4t(frag_addr(sb + O_FBL + bs * 4352, lane, coff), r0, r1, r2, r3);
            bL[2 * p][0] = r0; bL[2 * p][1] = r2;
            bL[2 * p + 1][0] = r1; bL[2 * p + 1][1] = r3;
        }
#pragma unroll
        for (int mt = 0; mt < 4; mt++)
#pragma unroll
            for (int nt = 0; nt < 4; nt++) {
                mma16816(acc[mt][nt], aH[mt][0], aH[mt][1], aH[mt][2], aH[mt][3],
                         bH[nt][0], bH[nt][1]);
                mma16816(acc[mt][nt], aH[mt][0], aH[mt][1], aH[mt][2], aH[mt][3],
                         bL[nt][0], bL[nt][1]);
                mma16816(acc[mt][nt], aL[mt][0], aL[mt][1], aL[mt][2], aL[mt][3],
                         bH[nt][0], bH[nt][1]);
            }
    }

    const int g = lane >> 2, tig = lane & 3;
    const float* rb = g_r + b * D_;
    float* Ob = outp + ((long)b * N_ + m0) * D_;
#pragma unroll
    for (int mt = 0; mt < 4; mt++)
#pragma unroll
        for (int nt = 0; nt < 4; nt++) {
            int row = wj * 64 + mt * 16 + g;
            int col = n0 + wl * 32 + nt * 8 + 2 * tig;
            float2 o0, o1;
            o0.x = acc[mt][nt][0] + rb[col];
            o0.y = acc[mt][nt][1] + rb[col + 1];
            o1.x = acc[mt][nt][2] + rb[col];
            o1.y = acc[mt][nt][3] + rb[col + 1];
            *(float2*)(Ob + (long)row * D_ + col) = o0;
            *(float2*)(Ob + (long)(row + 8) * D_ + col) = o1;
        }
}

// ---------------- small SIMT GEMM (256x256) ----------------
template <int BM, int BN, int TM, int TN, int KSTEP, bool AKM, int EPI>
__global__ void __launch_bounds__((BM / TM) * (BN / TN)) gemm_tpl(
    const float* __restrict__ Ag, const float* __restrict__ Bg, float* __restrict__ Cg,
    long sAb, long sBb, long sCb,
    const float* __restrict__ bkv, const float* __restrict__ bvv, float scale)
{
    constexpr int TX = BN / TN;
    constexpr int TY = BM / TM;
    constexpr int NT = TX * TY;

    const int t  = threadIdx.x;
    const int tx = t % TX;
    const int ty = t / TX;
    const int b  = blockIdx.z;

    const float* A  = Ag + (long)b * sAb;
    const float* Bm = Bg + (long)b * sBb;
    float*       C  = Cg + (long)b * sCb;

    const int m0 = blockIdx.y * BM;
    const int n0 = blockIdx.x * BN;

    __shared__ float sA[AKM ? (KSTEP * BM) : (BM * (KSTEP + 1))];
    __shared__ float sB[KSTEP * BN];

    unsigned long long acc[TM][TN / 2];
#pragma unroll
    for (int i = 0; i < TM; i++)
#pragma unroll
        for (int j = 0; j < TN / 2; j++) acc[i][j] = 0ull;

    for (int k0 = 0; k0 < D_; k0 += KSTEP) {
        if constexpr (AKM) {
            constexpr int AF4 = KSTEP * BM / 4;
#pragma unroll
            for (int r = 0; r < AF4 / NT; r++) {
                int i  = t + r * NT;
                int kk = i / (BM / 4);
                int mq = i % (BM / 4);
                float4 v = *(const float4*)(A + (long)(k0 + kk) * D_ + m0 + mq * 4);
                *(float4*)(&sA[kk * BM + mq * 4]) = v;
            }
        } else {
            constexpr int AF4 = BM * (KSTEP / 4);
#pragma unroll
            for (int r = 0; r < AF4 / NT; r++) {
                int i  = t + r * NT;
                int mr = i / (KSTEP / 4);
                int kq = i % (KSTEP / 4);
                float4 v = *(const float4*)(A + (long)(m0 + mr) * D_ + k0 + kq * 4);
                int base = mr * (KSTEP + 1) + kq * 4;
                sA[base + 0] = v.x; sA[base + 1] = v.y;
                sA[base + 2] = v.z; sA[base + 3] = v.w;
            }
        }
        {
            constexpr int BF4 = KSTEP * BN / 4;
#pragma unroll
            for (int r = 0; r < BF4 / NT; r++) {
                int i  = t + r * NT;
                int kk = i / (BN / 4);
                int nq = i % (BN / 4);
                float4 v = *(const float4*)(Bm + (long)(k0 + kk) * D_ + n0 + nq * 4);
                *(float4*)(&sB[kk * BN + nq * 4]) = v;
            }
        }
        __syncthreads();

#pragma unroll 4
        for (int kk = 0; kk < KSTEP; kk++) {
            unsigned long long bb[TN / 2];
            const unsigned long long* bp =
                reinterpret_cast<const unsigned long long*>(&sB[kk * BN + tx * TN]);
#pragma unroll
            for (int j = 0; j < TN / 2; j++) bb[j] = bp[j];

            float av[TM];
            if constexpr (AKM) {
#pragma unroll
                for (int q = 0; q < TM / 4; q++) {
                    float4 va = *(const float4*)(&sA[kk * BM + ty * TM + q * 4]);
                    av[q * 4 + 0] = va.x; av[q * 4 + 1] = va.y;
                    av[q * 4 + 2] = va.z; av[q * 4 + 3] = va.w;
                }
            } else {
#pragma unroll
                for (int i = 0; i < TM; i++)
                    av[i] = sA[(ty * TM + i) * (KSTEP + 1) + kk];
            }
#pragma unroll
            for (int i = 0; i < TM; i++) {
                unsigned long long aa = pack2(av[i], av[i]);
#pragma unroll
                for (int j = 0; j < TN / 2; j++) ffma2(acc[i][j], aa, bb[j]);
            }
        }
        __syncthreads();
    }

#pragma unroll
    for (int i = 0; i < TM; i++) {
        int m = m0 + ty * TM + i;
        float vals[TN];
#pragma unroll
        for (int j = 0; j < TN / 2; j++) unpack2(acc[i][j], vals[2 * j], vals[2 * j + 1]);
        float* crow = C + (long)m * D_ + n0 + tx * TN;

        if constexpr (EPI == 2) {
            float um  = g_u[b * D_ + m];
            float bkm = bkv[m];
            float cb  = g_cnt[b];
#pragma unroll
            for (int j = 0; j < TN; j++) {
                int col = n0 + tx * TN + j;
                crow[j] = scale * (vals[j] + um * bvv[col] + bkm * g_w[b * D_ + col]
                                   + cb * bkm * bvv[col]);
            }
        } else {
#pragma unroll
            for (int q = 0; q < TN / 4; q++) {
                float4 o;
                o.x = vals[q * 4 + 0]; o.y = vals[q * 4 + 1];
                o.z = vals[q * 4 + 2]; o.w = vals[q * 4 + 3];
                *(float4*)(&crow[q * 4]) = o;
            }
        }
    }
}

// ---------------- small kernels ----------------
__global__ void k_zero() {
    int i = blockIdx.x * blockDim.x + threadIdx.x;
    if (i < B_ * D_ * D_) g_G[i] = 0.0f;
    if (i < B_ * D_) { g_sk[i] = 0.0f; g_sv[i] = 0.0f; g_r[i] = 0.0f; }
    if (i < B_) g_cnt[i] = 0.0f;
    if (i == 0) { g_notint = 0; g_notfloat = 0; }
}

__global__ void k_flag(const float* __restrict__ bk, const float* __restrict__ bv,
                       const float* __restrict__ bq) {
    __shared__ float red[D_], redq[D_];
    int t = threadIdx.x;
    red[t]  = fabsf(bk[t]) + fabsf(bv[t]);
    redq[t] = fabsf(bq[t]);
    __syncthreads();
    for (int s = 128; s > 0; s >>= 1) {
        if (t < s) { red[t] += red[t + s]; redq[t] += redq[t + s]; }
        __syncthreads();
    }
    if (t == 0) { g_biasflag = red[0]; g_biasflagq = redq[0]; }
}

__global__ void k_tr(const float* __restrict__ Wv) {
    g_WvT[blockIdx.x * D_ + threadIdx.x] = Wv[threadIdx.x * D_ + blockIdx.x];
}

__global__ void k_sums(const float* __restrict__ key, const float* __restrict__ val) {
    if (g_biasflag == 0.0f) return;
    int b = blockIdx.x;
    int d = threadIdx.x;
    float sk = 0.0f, sv = 0.0f, c = 0.0f;
    for (int n = 0; n < N_; n++) {
        float ml = g_mask8[(long)b * N_ + n] ? 0.0f : 1.0f;
        sk += ml * key[((long)b * N_ + n) * D_ + d];
        sv += ml * val[((long)b * N_ + n) * D_ + d];
        c  += ml;
    }
    g_sk[b * D_ + d] = sk;
    g_sv[b * D_ + d] = sv;
    if (d == 0) g_cnt[b] = c;
}

__global__ void k_uw(const float* __restrict__ Wk, const float* __restrict__ Wv) {
    if (g_biasflag == 0.0f) {
        g_u[blockIdx.x * D_ + threadIdx.x] = 0.0f;
        g_w[blockIdx.x * D_ + threadIdx.x] = 0.0f;
        return;
    }
    int b = blockIdx.x;
    int d = threadIdx.x;
    float u = 0.0f, w = 0.0f;
    for (int j = 0; j < D_; j++) {
        u += Wk[d * D_ + j] * g_sk[b * D_ + j];
        w += g_sv[b * D_ + j] * Wv[d * D_ + j];
    }
    g_u[b * D_ + d] = u;
    g_w[b * D_ + d] = w;
}

// coalesced softmax over d: grid (B, 8), block 256; warp w covers d-range,
// lanes cover 32 consecutive e-columns.
__global__ void k_softmax() {
    __shared__ float pm[8][33], cmv[32], ps[8][33], csv[32];
    int b = blockIdx.x, eg = blockIdx.y;
    int lane = threadIdx.x & 31, w = threadIdx.x >> 5;
    float* S = g_S + (long)b * D_ * D_ + eg * 32;

    float mx = -1e30f;
#pragma unroll 4
    for (int dd = 0; dd < 32; dd++)
        mx = fmaxf(mx, S[(w * 32 + dd) * D_ + lane]);
    pm[w][lane] = mx;
    __syncthreads();
    if (w == 0) {
        float m2 = -1e30f;
#pragma unroll
        for (int q = 0; q < 8; q++) m2 = fmaxf(m2, pm[q][lane]);
        cmv[lane] = m2;
    }
    __syncthreads();
    float cmx = cmv[lane];
    float sum = 0.0f;
#pragma unroll 4
    for (int dd = 0; dd < 32; dd++) {
        float v = expf(S[(w * 32 + dd) * D_ + lane] - cmx);
        S[(w * 32 + dd) * D_ + lane] = v;
        sum += v;
    }
    ps[w][lane] = sum;
    __syncthreads();
    if (w == 0) {
        float s2 = 0.0f;
#pragma unroll
        for (int q = 0; q < 8; q++) s2 += ps[q][lane];
        csv[lane] = 1.0f / s2;
    }
    __syncthreads();
    float inv = csv[lane];
#pragma unroll 4
    for (int dd = 0; dd < 32; dd++)
        S[(w * 32 + dd) * D_ + lane] *= inv;
}

__global__ void k_r(const float* __restrict__ bq) {
    if (g_biasflagq == 0.0f) return;    // g_r already zeroed
    int b = blockIdx.x;
    int e = threadIdx.x;
    float r = 0.0f;
    for (int d = 0; d < D_; d++) r += bq[d] * g_S[(long)b * D_ * D_ + d * D_ + e];
    g_r[b * D_ + e] = r;
}

__global__ void k_split() {
    int i = blockIdx.x * blockDim.x + threadIdx.x;   // [0, B*D*D)
    float x = g_C[i];
    __half h = __float2half(x);
    g_CTh[i] = h;
    g_CTl[i] = __float2half(x - __half2float(h));
}

// ---------------- launch ----------------
extern "C" void kernel_launch(void* const* d_in, const int* in_sizes, int n_in,
                              void* d_out, int out_size)
{
    const float* query = (const float*)d_in[0];
    const float* key   = (const float*)d_in[1];
    const float* value = (const float*)d_in[2];
    const void*  maskp = d_in[3];

    int wbase = 4;
    if (wbase < n_in && in_sizes[wbase] < 32) wbase++;   // skip need_weights scalar

    const float* Wq = (const float*)d_in[wbase + 0];
    const float* bq = (const float*)d_in[wbase + 1];
    const float* Wk = (const float*)d_in[wbase + 2];
    const float* bk = (const float*)d_in[wbase + 3];
    const float* Wv = (const float*)d_in[wbase + 4];
    const float* bv = (const float*)d_in[wbase + 5];
    float* out = (float*)d_out;

    float *pG, *pT, *pS, *pC, *pWvT;
    cudaGetSymbolAddress((void**)&pG, g_G);
    cudaGetSymbolAddress((void**)&pT, g_T);
    cudaGetSymbolAddress((void**)&pS, g_S);
    cudaGetSymbolAddress((void**)&pC, g_C);
    cudaGetSymbolAddress((void**)&pWvT, g_WvT);

    cudaFuncSetAttribute(gemm_gram_mma, cudaFuncAttributeMaxDynamicSharedMemorySize, G_SMEM);
    cudaFuncSetAttribute(gemm_out_mma,  cudaFuncAttributeMaxDynamicSharedMemorySize, O_SMEM);

    const float scale = 0.3535533905932738f;  // 1/sqrt(B)

    k_zero<<<(B_ * D_ * D_ + 255) / 256, 256>>>();                       // 1
    k_maskdetect<<<16384 / 256, 256>>>(maskp);                           // 2
    k_maskconv<<<(B_ * N_) / 256, 256>>>(maskp);                         // 3

    // 4 (ncu slot): fused G via HMMA (fp32 in, convert+mask in-kernel)
    gemm_gram_mma<<<dim3(2, 2, B_ * GCH), 256, G_SMEM>>>(key, value);

    k_flag<<<1, D_>>>(bk, bv, bq);                                       // 5
    k_tr<<<D_, D_>>>(Wv);                                                // 6
    k_sums<<<B_, D_>>>(key, value);                                      // 7
    k_uw<<<B_, D_>>>(Wk, Wv);                                            // 8

    // T = Wk @ G
    gemm_tpl<64, 64, 4, 4, 32, false, 0>
        <<<dim3(4, 4, B_), 256>>>(Wk, pG, pT, 0L, (long)D_ * D_, (long)D_ * D_,
                                  nullptr, nullptr, 0.0f);
    // S = scale * (T @ WvT + bias terms)
    gemm_tpl<64, 64, 4, 4, 32, false, 2>
        <<<dim3(4, 4, B_), 256>>>(pT, pWvT, pS, (long)D_ * D_, 0L, (long)D_ * D_,
                                  bk, bv, scale);

    k_softmax<<<dim3(B_, 8), 256>>>();
    k_r<<<B_, D_>>>(bq);

    // C[d][e] = sum_dd Wq[dd][d] * aw[dd][e]
    gemm_tpl<64, 64, 4, 4, 32, true, 0>
        <<<dim3(4, 4, B_), 256>>>(Wq, pS, pC, 0L, (long)D_ * D_, (long)D_ * D_,
                                  nullptr, nullptr, 0.0f);
    k_split<<<(B_ * D_ * D_) / 256, 256>>>();

    // out = query @ C + r via HMMA
    gemm_out_mma<<<dim3(2, 64, B_), 256, O_SMEM>>>(query, out);
}